// round 6
// baseline (speedup 1.0000x reference)
#include <cuda_runtime.h>

// PushingEnv: B independent 2-body contact sims, H=200 Euler steps.
//
// Algebraic restructuring (C=1, DT=0.01, K=100, K*DT = 1 exactly):
//   sum coords  s = x1+x2, sv = v1+v2: contact force cancels ->
//       closed form s_H = s0 + C_SUM*sv0   (C_SUM = sum 0.01*0.99^n)
//   diff coords w = x1-x2:
//       a := -0.02*(w+1), q := 0.01*(v1-v2)
//       per step: r = min(a,0); q = 0.99*q + r; a = a - 0.02*q
//     -> 3 SASS instr/step/env: FMNMX (alu) + 2x FFMA-imm (fma, rt=1).
//   recover w = -50*a - 1; x1=(s+w)/2; x2=(s-w)/2; loss=(x2-goal)^2.
//
// R6 (= R5 resubmit; infra failure last round): scalar with ILP=2.
// Two independent chains per thread double per-warp issue density to kill
// the 28% scheduler bubbles R1 measured, at identical total instr count.

constexpr int H = 200;

constexpr float compute_c_sum() {
    float sv = 1.0f, s = 0.0f;
    for (int i = 0; i < H; ++i) { sv *= 0.99f; s += 0.01f * sv; }
    return s;
}
constexpr float C_SUM = compute_c_sum();

__global__ void __launch_bounds__(128) pushing_env_kernel(
    const float* __restrict__ x1_0,
    const float* __restrict__ v1_0,
    const float* __restrict__ x2_0,
    const float* __restrict__ v2_0,
    const float* __restrict__ goal,
    float* __restrict__ out,
    int n)
{
    int i = blockIdx.x * blockDim.x + threadIdx.x;  // pair index
    int j = 2 * i;
    if (j >= n) return;

    if (j + 1 < n) {
        float2 X1 = *(const float2*)(x1_0 + j);
        float2 V1 = *(const float2*)(v1_0 + j);
        float2 X2 = *(const float2*)(x2_0 + j);
        float2 V2 = *(const float2*)(v2_0 + j);
        float2 G  = *(const float2*)(goal + j);

        // two independent scalar difference-mode chains
        float q0 = 0.01f * (V1.x - V2.x);
        float a0 = fmaf(X1.x - X2.x, -0.02f, -0.02f);
        float q1 = 0.01f * (V1.y - V2.y);
        float a1 = fmaf(X1.y - X2.y, -0.02f, -0.02f);

        #pragma unroll
        for (int t = 0; t < H; ++t) {
            float r0 = fminf(a0, 0.0f);
            float r1 = fminf(a1, 0.0f);
            q0 = fmaf(q0, 0.99f, r0);
            q1 = fmaf(q1, 0.99f, r1);
            a0 = fmaf(q0, -0.02f, a0);
            a1 = fmaf(q1, -0.02f, a1);
        }

        float w0 = fmaf(a0, -50.0f, -1.0f);
        float w1 = fmaf(a1, -50.0f, -1.0f);

        // sum-mode closed form
        float s0 = fmaf(V1.x + V2.x, C_SUM, X1.x + X2.x);
        float s1 = fmaf(V1.y + V2.y, C_SUM, X1.y + X2.y);

        float2 xf1 = make_float2(0.5f * (s0 + w0), 0.5f * (s1 + w1));
        float2 xf2 = make_float2(0.5f * (s0 - w0), 0.5f * (s1 - w1));
        float d0 = xf2.x - G.x;
        float d1 = xf2.y - G.y;

        *(float2*)(out + j)         = make_float2(d0 * d0, d1 * d1);
        *(float2*)(out + n + j)     = xf1;
        *(float2*)(out + 2 * n + j) = xf2;
    } else {
        // scalar tail (n odd; not hit for B=262144)
        float x1 = x1_0[j], v1 = v1_0[j], x2 = x2_0[j], v2 = v2_0[j];
        float q = 0.01f * (v1 - v2);
        float a = fmaf(x1 - x2, -0.02f, -0.02f);
        #pragma unroll
        for (int t = 0; t < H; ++t) {
            float r = fminf(a, 0.0f);
            q = fmaf(q, 0.99f, r);
            a = fmaf(q, -0.02f, a);
        }
        float w = fmaf(a, -50.0f, -1.0f);
        float s = fmaf(v1 + v2, C_SUM, x1 + x2);
        float xf1 = 0.5f * (s + w);
        float xf2 = 0.5f * (s - w);
        float d = xf2 - goal[j];
        out[j] = d * d;
        out[n + j] = xf1;
        out[2 * n + j] = xf2;
    }
}

extern "C" void kernel_launch(void* const* d_in, const int* in_sizes, int n_in,
                              void* d_out, int out_size)
{
    // inputs: [0]=u_seq(H) [1]=x1_0 [2]=v1_0 [3]=x2_0 [4]=v2_0 [5]=goal [6]=gtype
    const float* x1_0 = (const float*)d_in[1];
    const float* v1_0 = (const float*)d_in[2];
    const float* x2_0 = (const float*)d_in[3];
    const float* v2_0 = (const float*)d_in[4];
    const float* goal = (const float*)d_in[5];
    int n = in_sizes[1];

    int threads = 128;
    int pairs = (n + 1) / 2;
    int blocks = (pairs + threads - 1) / threads;
    pushing_env_kernel<<<blocks, threads>>>(x1_0, v1_0, x2_0, v2_0, goal,
                                            (float*)d_out, n);
}

// round 7
// speedup vs baseline: 1.1261x; 1.1261x over previous
#include <cuda_runtime.h>
#include <cstdint>

// PushingEnv: B independent 2-body contact sims, H=200 Euler steps.
//
// Algebraic restructuring (C=1, DT=0.01, K=100, K*DT = 1 exactly):
//   sum coords  s = x1+x2, sv = v1+v2: contact force cancels ->
//       closed form s_H = s0 + C_SUM*sv0   (C_SUM = sum 0.01*0.99^n)
//   diff coords w = x1-x2:
//       a := -0.02*(w+1), q := 0.01*(v1-v2)
//       per step: r = min(a,0); q = 0.99*q + r; a = a - 0.02*q
//   recover w = -50*a - 1; x1=(s+w)/2; x2=(s-w)/2; loss=(x2-goal)^2.
//
// R7: best measured ingredients combined.
//   - packed f32x2 step via single asm block (R4-style; back-solved SASS
//     count confirmed mov elision: 2xFMNMX + 2xFFMA2 per step for 2 envs)
//   - ONE chain per thread (2 envs) -> 4096 warps (max for packed form;
//     R4's 2-chain/2048-warp variant starved on ramp/drain)
//   - 64-thread blocks -> 2048 blocks -> 13.84 blocks/SM (3.6% imbalance
//     vs 7% at 128thr / 15% at 256thr)

constexpr int H = 200;

constexpr float compute_c_sum() {
    float sv = 1.0f, s = 0.0f;
    for (int i = 0; i < H; ++i) { sv *= 0.99f; s += 0.01f * sv; }
    return s;
}
constexpr float C_SUM = compute_c_sum();

__device__ __forceinline__ uint64_t pack2(float lo, float hi) {
    uint64_t d;
    asm("mov.b64 %0, {%1, %2};" : "=l"(d) : "f"(lo), "f"(hi));
    return d;
}
__device__ __forceinline__ void unpack2(uint64_t d, float& lo, float& hi) {
    asm("mov.b64 {%0, %1}, %2;" : "=f"(lo), "=f"(hi) : "l"(d));
}

// One recurrence step on a packed pair-of-envs (Q, A):
//   r = min(a, 0) per half;  Q = Q*0.99 + r;  A = Q*(-0.02) + A
// Written as one contiguous block with fresh virtual regs so ptxas
// coalesces the pair splits/joins away (verified via issued-instr count).
#define STEP(Q, A, C99, CM02)                                      \
    asm("{\n\t"                                                    \
        ".reg .f32 al, ah, rl, rh;\n\t"                            \
        ".reg .b64 r;\n\t"                                         \
        "mov.b64 {al, ah}, %1;\n\t"                                \
        "min.f32 rl, al, 0f00000000;\n\t"                          \
        "min.f32 rh, ah, 0f00000000;\n\t"                          \
        "mov.b64 r, {rl, rh};\n\t"                                 \
        "fma.rn.f32x2 %0, %0, %2, r;\n\t"                          \
        "fma.rn.f32x2 %1, %0, %3, %1;\n\t"                         \
        "}"                                                        \
        : "+l"(Q), "+l"(A) : "l"(C99), "l"(CM02))

__global__ void __launch_bounds__(64) pushing_env_kernel(
    const float* __restrict__ x1_0,
    const float* __restrict__ v1_0,
    const float* __restrict__ x2_0,
    const float* __restrict__ v2_0,
    const float* __restrict__ goal,
    float* __restrict__ out,
    int n)
{
    int i = blockIdx.x * blockDim.x + threadIdx.x;  // pair index
    int j = 2 * i;
    if (j >= n) return;

    if (j + 1 < n) {
        // front-batched loads, MLP=5
        float2 X1 = *(const float2*)(x1_0 + j);
        float2 V1 = *(const float2*)(v1_0 + j);
        float2 X2 = *(const float2*)(x2_0 + j);
        float2 V2 = *(const float2*)(v2_0 + j);
        float2 G  = *(const float2*)(goal + j);

        // packed difference-mode chain (2 envs)
        uint64_t Q = pack2(0.01f * (V1.x - V2.x), 0.01f * (V1.y - V2.y));
        uint64_t A = pack2(fmaf(X1.x - X2.x, -0.02f, -0.02f),
                           fmaf(X1.y - X2.y, -0.02f, -0.02f));

        const uint64_t C99  = pack2(0.99f, 0.99f);
        const uint64_t CM02 = pack2(-0.02f, -0.02f);

        #pragma unroll
        for (int t = 0; t < H; ++t) {
            STEP(Q, A, C99, CM02);
        }

        float a0, a1;
        unpack2(A, a0, a1);
        float w0 = fmaf(a0, -50.0f, -1.0f);
        float w1 = fmaf(a1, -50.0f, -1.0f);

        // sum-mode closed form
        float s0 = fmaf(V1.x + V2.x, C_SUM, X1.x + X2.x);
        float s1 = fmaf(V1.y + V2.y, C_SUM, X1.y + X2.y);

        float2 xf1 = make_float2(0.5f * (s0 + w0), 0.5f * (s1 + w1));
        float2 xf2 = make_float2(0.5f * (s0 - w0), 0.5f * (s1 - w1));
        float d0 = xf2.x - G.x;
        float d1 = xf2.y - G.y;

        *(float2*)(out + j)         = make_float2(d0 * d0, d1 * d1);
        *(float2*)(out + n + j)     = xf1;
        *(float2*)(out + 2 * n + j) = xf2;
    } else {
        // scalar tail (n odd; not hit for B=262144)
        float x1 = x1_0[j], v1 = v1_0[j], x2 = x2_0[j], v2 = v2_0[j];
        float q = 0.01f * (v1 - v2);
        float a = fmaf(x1 - x2, -0.02f, -0.02f);
        #pragma unroll
        for (int t = 0; t < H; ++t) {
            float r = fminf(a, 0.0f);
            q = fmaf(q, 0.99f, r);
            a = fmaf(q, -0.02f, a);
        }
        float w = fmaf(a, -50.0f, -1.0f);
        float s = fmaf(v1 + v2, C_SUM, x1 + x2);
        float xf1 = 0.5f * (s + w);
        float xf2 = 0.5f * (s - w);
        float d = xf2 - goal[j];
        out[j] = d * d;
        out[n + j] = xf1;
        out[2 * n + j] = xf2;
    }
}

extern "C" void kernel_launch(void* const* d_in, const int* in_sizes, int n_in,
                              void* d_out, int out_size)
{
    // inputs: [0]=u_seq(H) [1]=x1_0 [2]=v1_0 [3]=x2_0 [4]=v2_0 [5]=goal [6]=gtype
    const float* x1_0 = (const float*)d_in[1];
    const float* v1_0 = (const float*)d_in[2];
    const float* x2_0 = (const float*)d_in[3];
    const float* v2_0 = (const float*)d_in[4];
    const float* goal = (const float*)d_in[5];
    int n = in_sizes[1];

    int threads = 64;
    int pairs = (n + 1) / 2;
    int blocks = (pairs + threads - 1) / threads;
    pushing_env_kernel<<<blocks, threads>>>(x1_0, v1_0, x2_0, v2_0, goal,
                                            (float*)d_out, n);
}

// round 8
// speedup vs baseline: 1.1719x; 1.0406x over previous
#include <cuda_runtime.h>
#include <cstdint>

// PushingEnv: B independent 2-body contact sims, H=200 Euler steps.
//
// Algebraic restructuring (C=1, DT=0.01, K=100, K*DT = 1 exactly):
//   sum coords  s = x1+x2, sv = v1+v2: contact force cancels ->
//       closed form s_H = s0 + C_SUM*sv0   (C_SUM = sum 0.01*0.99^n)
//   diff coords w = x1-x2:
//       a := -0.02*(w+1), q := 0.01*(v1-v2)
//       per step: r = min(a,0); q = 0.99*q + r; a = a - 0.02*q
//   recover w = -50*a - 1; x1=(s+w)/2; x2=(s-w)/2; loss=(x2-goal)^2.
//
// R8: packed f32x2 chain (confirmed ~4 instr/step/2envs, lowest measured
// instruction count) + 256-thread blocks. Cross-round data fits the
// cross-CTA L1tex spread model: issue% degraded with blocks/SM
// (64thr/13.8 blk/SM -> 53.7%, 256thr/6.9 -> 71.7%). 512 blocks at
// 3.46/SM puts oe*MLP_p1 at the contention threshold -> minimal spread.

constexpr int H = 200;

constexpr float compute_c_sum() {
    float sv = 1.0f, s = 0.0f;
    for (int i = 0; i < H; ++i) { sv *= 0.99f; s += 0.01f * sv; }
    return s;
}
constexpr float C_SUM = compute_c_sum();

__device__ __forceinline__ uint64_t pack2(float lo, float hi) {
    uint64_t d;
    asm("mov.b64 %0, {%1, %2};" : "=l"(d) : "f"(lo), "f"(hi));
    return d;
}
__device__ __forceinline__ void unpack2(uint64_t d, float& lo, float& hi) {
    asm("mov.b64 {%0, %1}, %2;" : "=f"(lo), "=f"(hi) : "l"(d));
}

// One recurrence step on a packed pair-of-envs (Q, A):
//   r = min(a, 0) per half;  Q = Q*0.99 + r;  A = Q*(-0.02) + A
#define STEP(Q, A, C99, CM02)                                      \
    asm("{\n\t"                                                    \
        ".reg .f32 al, ah, rl, rh;\n\t"                            \
        ".reg .b64 r;\n\t"                                         \
        "mov.b64 {al, ah}, %1;\n\t"                                \
        "min.f32 rl, al, 0f00000000;\n\t"                          \
        "min.f32 rh, ah, 0f00000000;\n\t"                          \
        "mov.b64 r, {rl, rh};\n\t"                                 \
        "fma.rn.f32x2 %0, %0, %2, r;\n\t"                          \
        "fma.rn.f32x2 %1, %0, %3, %1;\n\t"                         \
        "}"                                                        \
        : "+l"(Q), "+l"(A) : "l"(C99), "l"(CM02))

__global__ void __launch_bounds__(256) pushing_env_kernel(
    const float* __restrict__ x1_0,
    const float* __restrict__ v1_0,
    const float* __restrict__ x2_0,
    const float* __restrict__ v2_0,
    const float* __restrict__ goal,
    float* __restrict__ out,
    int n)
{
    int i = blockIdx.x * blockDim.x + threadIdx.x;  // pair index
    int j = 2 * i;
    if (j >= n) return;

    if (j + 1 < n) {
        float2 X1 = *(const float2*)(x1_0 + j);
        float2 V1 = *(const float2*)(v1_0 + j);
        float2 X2 = *(const float2*)(x2_0 + j);
        float2 V2 = *(const float2*)(v2_0 + j);
        float2 G  = *(const float2*)(goal + j);

        // packed difference-mode chain (2 envs)
        uint64_t Q = pack2(0.01f * (V1.x - V2.x), 0.01f * (V1.y - V2.y));
        uint64_t A = pack2(fmaf(X1.x - X2.x, -0.02f, -0.02f),
                           fmaf(X1.y - X2.y, -0.02f, -0.02f));

        const uint64_t C99  = pack2(0.99f, 0.99f);
        const uint64_t CM02 = pack2(-0.02f, -0.02f);

        #pragma unroll
        for (int t = 0; t < H; ++t) {
            STEP(Q, A, C99, CM02);
        }

        float a0, a1;
        unpack2(A, a0, a1);
        float w0 = fmaf(a0, -50.0f, -1.0f);
        float w1 = fmaf(a1, -50.0f, -1.0f);

        // sum-mode closed form
        float s0 = fmaf(V1.x + V2.x, C_SUM, X1.x + X2.x);
        float s1 = fmaf(V1.y + V2.y, C_SUM, X1.y + X2.y);

        float2 xf1 = make_float2(0.5f * (s0 + w0), 0.5f * (s1 + w1));
        float2 xf2 = make_float2(0.5f * (s0 - w0), 0.5f * (s1 - w1));
        float d0 = xf2.x - G.x;
        float d1 = xf2.y - G.y;

        *(float2*)(out + j)         = make_float2(d0 * d0, d1 * d1);
        *(float2*)(out + n + j)     = xf1;
        *(float2*)(out + 2 * n + j) = xf2;
    } else {
        // scalar tail (n odd; not hit for B=262144)
        float x1 = x1_0[j], v1 = v1_0[j], x2 = x2_0[j], v2 = v2_0[j];
        float q = 0.01f * (v1 - v2);
        float a = fmaf(x1 - x2, -0.02f, -0.02f);
        #pragma unroll
        for (int t = 0; t < H; ++t) {
            float r = fminf(a, 0.0f);
            q = fmaf(q, 0.99f, r);
            a = fmaf(q, -0.02f, a);
        }
        float w = fmaf(a, -50.0f, -1.0f);
        float s = fmaf(v1 + v2, C_SUM, x1 + x2);
        float xf1 = 0.5f * (s + w);
        float xf2 = 0.5f * (s - w);
        float d = xf2 - goal[j];
        out[j] = d * d;
        out[n + j] = xf1;
        out[2 * n + j] = xf2;
    }
}

extern "C" void kernel_launch(void* const* d_in, const int* in_sizes, int n_in,
                              void* d_out, int out_size)
{
    // inputs: [0]=u_seq(H) [1]=x1_0 [2]=v1_0 [3]=x2_0 [4]=v2_0 [5]=goal [6]=gtype
    const float* x1_0 = (const float*)d_in[1];
    const float* v1_0 = (const float*)d_in[2];
    const float* x2_0 = (const float*)d_in[3];
    const float* v2_0 = (const float*)d_in[4];
    const float* goal = (const float*)d_in[5];
    int n = in_sizes[1];

    int threads = 256;
    int pairs = (n + 1) / 2;
    int blocks = (pairs + threads - 1) / threads;
    pushing_env_kernel<<<blocks, threads>>>(x1_0, v1_0, x2_0, v2_0, goal,
                                            (float*)d_out, n);
}